// round 14
// baseline (speedup 1.0000x reference)
#include <cuda_runtime.h>
#include <cuda_bf16.h>
#include <cstdint>
#include <cstddef>

// ---------------------------------------------------------------------------
// TTLinear. Phase A: 3 big tf32 tensor-core GEMMs. Phase B: one persistent
// kernel (256 thr/block, 1 block/SM), 128 steps, 8 regions (R10 structure —
// measured better than the fused 5-region variant). R14 changes vs R10:
//   * pair-interleaved smem layouts -> mma fragment loads are 3x LDS.64
//     instead of 6x LDS.32 per 8-k step
//   * one __syncthreads per k-slab (entry guard + double buffer)
//   * S10 and R6 use 3-mma split-tf32 (near-fp32) instead of fp32 SIMT
// ---------------------------------------------------------------------------

constexpr int T_  = 128;
constexpr int NB  = 256;
constexpr int DD  = 1024;
constexpr int HH  = 1024;
constexpr int H4  = 256;
constexpr int NH  = NB * HH;    // 262144
constexpr int MN  = NB * H4;    // 65536
constexpr float LR = 1e-3f;
constexpr float C2 = 2.0f / (float)(NB * HH);

constexpr int SLA = 66;         // A smem row stride (64 cols + 2 pad)
constexpr int SLB = 132;        // B smem row stride (64 cols x2 interleave + 4)
constexpr int ABUF = 16 * SLA;  // 1056
constexpr int BBUF = 16 * SLB;  // 2112

// ------------------------- device scratch ----------------------------------
__device__ float g_Z[(size_t)T_ * NH];
__device__ float g_Y[(size_t)T_ * NH];
__device__ float g_Q[(size_t)T_ * NH];
__device__ float g_W1[H4 * HH];
__device__ float g_b1[H4];
__device__ float g_W2[HH * H4];
__device__ float g_b2[HH];
__device__ float g_a[MN];
__device__ float g_h[MN];
__device__ float g_h2[MN];
__device__ float g_da[MN];
__device__ float g_dr[NB * HH];
__device__ float g_part[8 * MN];

__device__ __align__(128) unsigned g_cnt = 0;
__device__ __align__(128) unsigned g_gen = 0;

// ------------------------------ helpers ------------------------------------
__device__ __forceinline__ float gelu_f(float x) {
    return 0.5f * x * (1.0f + erff(x * 0.70710678118654752f));
}
__device__ __forceinline__ float gelu_grad(float x) {
    float cdf = 0.5f * (1.0f + erff(x * 0.70710678118654752f));
    float pdf = 0.3989422804014327f * expf(-0.5f * x * x);
    return cdf + x * pdf;
}
__device__ __forceinline__ float to_tf32(float x) {
    uint32_t u;
    asm("cvt.rna.tf32.f32 %0, %1;" : "=r"(u) : "f"(x));
    return __uint_as_float(u);
}
__device__ __forceinline__ void mma_tf32(float (&c)[4], const uint32_t (&a)[4],
                                         const uint32_t (&b)[2]) {
    asm volatile(
        "mma.sync.aligned.m16n8k8.row.col.f32.tf32.tf32.f32 "
        "{%0,%1,%2,%3}, {%4,%5,%6,%7}, {%8,%9}, {%0,%1,%2,%3};"
        : "+f"(c[0]), "+f"(c[1]), "+f"(c[2]), "+f"(c[3])
        : "r"(a[0]), "r"(a[1]), "r"(a[2]), "r"(a[3]), "r"(b[0]), "r"(b[1]));
}

// m-permutation: (m, m+8) within each 16-block become adjacent columns.
__device__ __forceinline__ int permM(int m) {
    return (m & ~15) | ((m & 7) << 1) | ((m & 15) >> 3);
}

// Hot-spin grid barrier, bounded (sync bug -> wrong output, not a hang).
__device__ __forceinline__ void grid_sync(unsigned nb) {
    __syncthreads();
    if (threadIdx.x == 0) {
        unsigned gen = *(volatile unsigned*)&g_gen;
        __threadfence();
        if (atomicAdd(&g_cnt, 1) == nb - 1) {
            g_cnt = 0;
            __threadfence();
            atomicAdd(&g_gen, 1);
        } else {
            for (int spin = 0; spin < 1000000; spin++) {
                if (*(volatile unsigned*)&g_gen != gen) break;
            }
        }
        __threadfence();
    }
    __syncthreads();
}

// ---------------------------------------------------------------------------
// Phase A: C[M,N] = A[M,K] @ B[N,K]^T via tf32 mma.sync (unchanged, passing).
// ---------------------------------------------------------------------------
__global__ __launch_bounds__(256, 2) void gemm_nt_tf32(
    const float* __restrict__ A, const float* __restrict__ B,
    float* __restrict__ C, int M, int N, int K)
{
    __shared__ float As[2][16][136];
    __shared__ float Bs[2][16][136];
    const int m0 = blockIdx.x * 128, n0 = blockIdx.y * 128;
    const int tid = threadIdx.x;
    const int lrow = tid & 127, lc8 = (tid >> 7) * 8;
    const int w = tid >> 5, lane = tid & 31;
    const int wm = w >> 2, wn = w & 3;
    const int g = lane >> 2, q = lane & 3;

    float acc[4][4][4] = {};
    const float* Ag = A + (size_t)(m0 + lrow) * K + lc8;
    const float* Bg = B + (size_t)(n0 + lrow) * K + lc8;

    float4 ra0 = *(const float4*)(Ag);
    float4 ra1 = *(const float4*)(Ag + 4);
    float4 rb0 = *(const float4*)(Bg);
    float4 rb1 = *(const float4*)(Bg + 4);

    const int S = K / 16;
    for (int s = 0; s < S; s++) {
        const int buf = s & 1;
        {
            float* pa = &As[buf][lc8][lrow];
            pa[0*136] = to_tf32(ra0.x); pa[1*136] = to_tf32(ra0.y);
            pa[2*136] = to_tf32(ra0.z); pa[3*136] = to_tf32(ra0.w);
            pa[4*136] = to_tf32(ra1.x); pa[5*136] = to_tf32(ra1.y);
            pa[6*136] = to_tf32(ra1.z); pa[7*136] = to_tf32(ra1.w);
            float* pb = &Bs[buf][lc8][lrow];
            pb[0*136] = to_tf32(rb0.x); pb[1*136] = to_tf32(rb0.y);
            pb[2*136] = to_tf32(rb0.z); pb[3*136] = to_tf32(rb0.w);
            pb[4*136] = to_tf32(rb1.x); pb[5*136] = to_tf32(rb1.y);
            pb[6*136] = to_tf32(rb1.z); pb[7*136] = to_tf32(rb1.w);
        }
        if (s + 1 < S) {
            const float* a2 = Ag + (s + 1) * 16;
            const float* b2 = Bg + (s + 1) * 16;
            ra0 = *(const float4*)(a2);     ra1 = *(const float4*)(a2 + 4);
            rb0 = *(const float4*)(b2);     rb1 = *(const float4*)(b2 + 4);
        }
        __syncthreads();
#pragma unroll
        for (int kc = 0; kc < 16; kc += 8) {
            uint32_t af[4][4], bf[4][2];
#pragma unroll
            for (int mt = 0; mt < 4; mt++) {
                int r = wm * 64 + mt * 16 + g;
                af[mt][0] = __float_as_uint(As[buf][kc + q][r]);
                af[mt][1] = __float_as_uint(As[buf][kc + q][r + 8]);
                af[mt][2] = __float_as_uint(As[buf][kc + q + 4][r]);
                af[mt][3] = __float_as_uint(As[buf][kc + q + 4][r + 8]);
            }
#pragma unroll
            for (int nt = 0; nt < 4; nt++) {
                int c = wn * 32 + nt * 8 + g;
                bf[nt][0] = __float_as_uint(Bs[buf][kc + q][c]);
                bf[nt][1] = __float_as_uint(Bs[buf][kc + q + 4][c]);
            }
#pragma unroll
            for (int mt = 0; mt < 4; mt++)
#pragma unroll
                for (int nt = 0; nt < 4; nt++)
                    mma_tf32(acc[mt][nt], af[mt], bf[nt]);
        }
        __syncthreads();
    }
#pragma unroll
    for (int mt = 0; mt < 4; mt++)
#pragma unroll
        for (int nt = 0; nt < 4; nt++) {
            int r = m0 + wm * 64 + mt * 16 + g;
            int c = n0 + wn * 32 + nt * 8 + q * 2;
            *(float2*)&C[(size_t)r * N + c] =
                make_float2(acc[mt][nt][0], acc[mt][nt][1]);
            *(float2*)&C[(size_t)(r + 8) * N + c] =
                make_float2(acc[mt][nt][2], acc[mt][nt][3]);
        }
}

// ---------------------------------------------------------------------------
// Phase B tile: TM x 64 output (TM=64 or 32), tf32 mma, pair-interleaved smem
// layouts, one sync per 16-k slab (entry guard + double buffer).
// MODE 0 NT: A[m,k],B[n,k]; MODE 1 NN: A[m,k],B[k,n]; MODE 2 TN: A[k,m],B[k,n]
// SPLIT 0: plain tf32 (gradient path); 1: 3-mma split-tf32 (output path).
// smem layout (floats): A 2 bufs x 1056 at 0; B 2 bufs x 2112 at 2112.
// A[k][permM(m)] (stride 66); B[(k&~7)|(k&3)][n*2 + ((k>>2)&1)] (stride 132).
// ---------------------------------------------------------------------------
template <int MODE, int TM, int SPLIT>
__device__ __forceinline__ void tile_mma(
    const float* __restrict__ A, const float* __restrict__ B, float* sm,
    int lda, int ldb, int m0, int n0, int kbeg, int kend,
    float (&acc)[TM / 32][2][4])
{
    const int tid = threadIdx.x;
    const int w = tid >> 5, lane = tid & 31;
    const int wm = w >> 2, wn = w & 3;
    const int g = lane >> 2, q = lane & 3;
    float* smA = sm;
    float* smB = sm + 2 * ABUF;
    const int nslab = (kend - kbeg) >> 4;

    // staging indices
    const int a_m64 = tid >> 2,  a_c64 = (tid & 3) * 4;   // MODE0/1, TM=64
    const int a_m32 = tid >> 3,  a_c32 = (tid & 7) * 2;   // MODE0/1, TM=32
    const int a_k   = tid >> 4,  a_m4  = (tid & 15) * 4;  // MODE2
    const int b_n   = tid >> 2,  b_c4  = (tid & 3) * 4;   // MODE0
    const int b_k   = tid >> 4,  b_n4  = (tid & 15) * 4;  // MODE1/2

    float4 ra, rb; float2 ra2;

    // prologue fetch (slab 0)
    {
        int k0 = kbeg;
        if (MODE == 2)      ra  = *(const float4*)(A + (size_t)(k0 + a_k) * lda + m0 + a_m4);
        else if (TM == 64)  ra  = *(const float4*)(A + (size_t)(m0 + a_m64) * lda + k0 + a_c64);
        else                ra2 = *(const float2*)(A + (size_t)(m0 + a_m32) * lda + k0 + a_c32);
        if (MODE == 0)      rb  = *(const float4*)(B + (size_t)(n0 + b_n) * ldb + k0 + b_c4);
        else                rb  = *(const float4*)(B + (size_t)(k0 + b_k) * ldb + n0 + b_n4);
    }

    __syncthreads();   // entry guard: prior tile's smem readers are done
    for (int s = 0; s < nslab; s++) {
        const int buf = s & 1;
        {   // store staged regs (permuted/pair-interleaved layouts)
            float* dA = smA + buf * ABUF;
            float* dB = smB + buf * BBUF;
            if (MODE == 2) {
                dA[a_k * SLA + permM(a_m4 + 0)] = ra.x;
                dA[a_k * SLA + permM(a_m4 + 1)] = ra.y;
                dA[a_k * SLA + permM(a_m4 + 2)] = ra.z;
                dA[a_k * SLA + permM(a_m4 + 3)] = ra.w;
            } else if (TM == 64) {
                int p = permM(a_m64);
                dA[(a_c64 + 0) * SLA + p] = ra.x;
                dA[(a_c64 + 1) * SLA + p] = ra.y;
                dA[(a_c64 + 2) * SLA + p] = ra.z;
                dA[(a_c64 + 3) * SLA + p] = ra.w;
            } else {
                int p = permM(a_m32);
                dA[(a_c32 + 0) * SLA + p] = ra2.x;
                dA[(a_c32 + 1) * SLA + p] = ra2.y;
            }
            if (MODE == 0) {
#pragma unroll
                for (int j = 0; j < 4; j++) {
                    int k = b_c4 + j;
                    int r2 = (k & ~7) | (k & 3);
                    int hf = (k >> 2) & 1;
                    dB[r2 * SLB + b_n * 2 + hf] = (&rb.x)[j];
                }
            } else {
                int r2 = (b_k & ~7) | (b_k & 3);
                int hf = (b_k >> 2) & 1;
                dB[r2 * SLB + (b_n4 + 0) * 2 + hf] = rb.x;
                dB[r2 * SLB + (b_n4 + 1) * 2 + hf] = rb.y;
                dB[r2 * SLB + (b_n4 + 2) * 2 + hf] = rb.z;
                dB[r2 * SLB + (b_n4 + 3) * 2 + hf] = rb.w;
            }
        }
        if (s + 1 < nslab) {   // prefetch next slab
            int k0 = kbeg + (s + 1) * 16;
            if (MODE == 2)      ra  = *(const float4*)(A + (size_t)(k0 + a_k) * lda + m0 + a_m4);
            else if (TM == 64)  ra  = *(const float4*)(A + (size_t)(m0 + a_m64) * lda + k0 + a_c64);
            else                ra2 = *(const float2*)(A + (size_t)(m0 + a_m32) * lda + k0 + a_c32);
            if (MODE == 0)      rb  = *(const float4*)(B + (size_t)(n0 + b_n) * ldb + k0 + b_c4);
            else                rb  = *(const float4*)(B + (size_t)(k0 + b_k) * ldb + n0 + b_n4);
        }
        __syncthreads();
        const float* cA = smA + buf * ABUF;
        const float* cB = smB + buf * BBUF;
#pragma unroll
        for (int kc = 0; kc < 16; kc += 8) {
            float2 xa[TM / 32], ya[TM / 32];
#pragma unroll
            for (int mt = 0; mt < TM / 32; mt++) {
                int base = wm * (TM / 2) + mt * 16 + g * 2;
                xa[mt] = *(const float2*)(cA + (kc + q) * SLA + base);
                ya[mt] = *(const float2*)(cA + (kc + q + 4) * SLA + base);
            }
            float2 xb[2];
#pragma unroll
            for (int nt = 0; nt < 2; nt++) {
                int c = wn * 16 + nt * 8 + g;
                xb[nt] = *(const float2*)(cB + (kc + q) * SLB + c * 2);
            }
            if (SPLIT == 0) {
#pragma unroll
                for (int mt = 0; mt < TM / 32; mt++) {
                    uint32_t af[4] = {__float_as_uint(xa[mt].x), __float_as_uint(xa[mt].y),
                                      __float_as_uint(ya[mt].x), __float_as_uint(ya[mt].y)};
#pragma unroll
                    for (int nt = 0; nt < 2; nt++) {
                        uint32_t bf[2] = {__float_as_uint(xb[nt].x), __float_as_uint(xb[nt].y)};
                        mma_tf32(acc[mt][nt], af, bf);
                    }
                }
            } else {
                // 3-mma split-tf32 (hi*hi + lo*hi + hi*lo)
                float ah[TM / 32][4], al[TM / 32][4];
#pragma unroll
                for (int mt = 0; mt < TM / 32; mt++) {
                    float v0 = xa[mt].x, v1 = xa[mt].y, v2 = ya[mt].x, v3 = ya[mt].y;
                    ah[mt][0] = to_tf32(v0); ah[mt][1] = to_tf32(v1);
                    ah[mt][2] = to_tf32(v2); ah[mt][3] = to_tf32(v3);
                    al[mt][0] = to_tf32(v0 - ah[mt][0]); al[mt][1] = to_tf32(v1 - ah[mt][1]);
                    al[mt][2] = to_tf32(v2 - ah[mt][2]); al[mt][3] = to_tf32(v3 - ah[mt][3]);
                }
                float bh[2][2], bl[2][2];
#pragma unroll
                for (int nt = 0; nt < 2; nt++) {
                    bh[nt][0] = to_tf32(xb[nt].x); bh[nt][1] = to_tf32(xb[nt].y);
                    bl[nt][0] = to_tf32(xb[nt].x - bh[nt][0]);
                    bl[nt][1] = to_tf32(xb[nt].y - bh[nt][1]);
                }
#pragma unroll
                for (int mt = 0; mt < TM / 32; mt++) {
                    uint32_t afh[4] = {__float_as_uint(ah[mt][0]), __float_as_uint(ah[mt][1]),
                                       __float_as_uint(ah[mt][2]), __float_as_uint(ah[mt][3])};
                    uint32_t afl[4] = {__float_as_uint(al[mt][0]), __float_as_uint(al[mt][1]),
                                       __float_as_uint(al[mt][2]), __float_as_uint(al[mt][3])};
#pragma unroll
                    for (int nt = 0; nt < 2; nt++) {
                        uint32_t bfh[2] = {__float_as_uint(bh[nt][0]), __float_as_uint(bh[nt][1])};
                        uint32_t bfl[2] = {__float_as_uint(bl[nt][0]), __float_as_uint(bl[nt][1])};
                        mma_tf32(acc[mt][nt], afh, bfh);
                        mma_tf32(acc[mt][nt], afl, bfh);
                        mma_tf32(acc[mt][nt], afh, bfl);
                    }
                }
            }
        }
    }
    __syncthreads();   // readers done before caller reuses smem
}

// ---------------------------------------------------------------------------
// Persistent Phase B kernel: 256 threads/block, one tile-unit per block/wave.
// Regions (R10 structure): R0 (S10 + S1 partials), R1 (reduce+gelu),
// R2 (dr), R3 (da partials), R4 (reduce+gelu'), R5 (W updates + biases),
// R6 (a2 partials), R7 (reduce+gelu). 8 grid barriers per step.
// ---------------------------------------------------------------------------
__global__ __launch_bounds__(256, 1) void ttt_persistent(float* __restrict__ out,
                                                         int nb)
{
    __shared__ __align__(16) float SM[2 * ABUF + 2 * BBUF];
    const int bid = blockIdx.x, tid = threadIdx.x;
    const int w = tid >> 5, lane = tid & 31;
    const int wm = w >> 2, wn = w & 3;
    const int g = lane >> 2, q = lane & 3;
    const int gw = (bid * 256 + tid) >> 5;

    for (int step = 0; step <= T_; step++) {
        // ---- R0: S10 of step-1 (split-tf32, 128 u, 32x64, K=256)
        //        + S1 partials of step (tf32, 128 u, 64x64, K=128) ----
        {
            const int nA = (step > 0) ? 128 : 0;
            const int nTot = nA + ((step < T_) ? 128 : 0);
            for (int u = bid; u < nTot; u += nb) {
                const int uu = (step > 0) ? u : u + 128;
                if (uu < 128) {
                    // S10: out[t-1] = Qt + h2 @ W2^T + b2 (split-tf32)
                    const int t = step - 1;
                    const float* Qt = g_Q + (size_t)t * NH;
                    float* od = out + (size_t)t * NH;
                    int m0 = (uu & 7) * 32, n0 = (uu >> 3) * 64;
                    float acc[1][2][4] = {};
                    tile_mma<0, 32, 1>(g_h2, g_W2, SM, H4, H4, m0, n0, 0, H4, acc);
#pragma unroll
                    for (int nt = 0; nt < 2; nt++) {
                        int m = m0 + wm * 16 + g;
                        int nn = n0 + wn * 16 + nt * 8 + q * 2;
                        float2 bb = *(const float2*)(g_b2 + nn);
                        {
                            float2 qv = *(const float2*)(Qt + (size_t)m * HH + nn);
                            *(float2*)(od + (size_t)m * HH + nn) = make_float2(
                                qv.x + acc[0][nt][0] + bb.x,
                                qv.y + acc[0][nt][1] + bb.y);
                        }
                        {
                            int m8 = m + 8;
                            float2 qv = *(const float2*)(Qt + (size_t)m8 * HH + nn);
                            *(float2*)(od + (size_t)m8 * HH + nn) = make_float2(
                                qv.x + acc[0][nt][2] + bb.x,
                                qv.y + acc[0][nt][3] + bb.y);
                        }
                    }
                } else {
                    // S1: part[sk] = Zt @ W1^T slice (tf32)
                    const int v = uu - 128;
                    const float* Zt = g_Z + (size_t)step * NH;
                    int sk = v & 7, tile = v >> 3;
                    int m0 = (tile & 3) * 64, n0 = (tile >> 2) * 64;
                    float acc[2][2][4] = {};
                    tile_mma<0, 64, 0>(Zt, g_W1, SM, DD, DD, m0, n0,
                                       sk * 128, sk * 128 + 128, acc);
                    float* cp = g_part + (size_t)sk * MN;
#pragma unroll
                    for (int mt = 0; mt < 2; mt++)
#pragma unroll
                        for (int nt = 0; nt < 2; nt++) {
                            int m = m0 + wm * 32 + mt * 16 + g;
                            int nn = n0 + wn * 16 + nt * 8 + q * 2;
                            *(float2*)(cp + (size_t)m * H4 + nn) =
                                make_float2(acc[mt][nt][0], acc[mt][nt][1]);
                            *(float2*)(cp + (size_t)(m + 8) * H4 + nn) =
                                make_float2(acc[mt][nt][2], acc[mt][nt][3]);
                        }
                }
            }
        }
        grid_sync(nb);
        if (step == T_) break;

        const int t = step;
        const float* Zt = g_Z + (size_t)t * NH;
        const float* Yt = g_Y + (size_t)t * NH;
        const float* Qt = g_Q + (size_t)t * NH;

        // ---- R1: a = sum(part)+b1; h = gelu(a) ----
        for (int idx = bid * 256 + tid; idx < MN; idx += nb * 256) {
            float s = 0.f;
#pragma unroll
            for (int z = 0; z < 8; z++) s += g_part[(size_t)z * MN + idx];
            s += g_b1[idx & (H4 - 1)];
            g_a[idx] = s;
            g_h[idx] = gelu_f(s);
        }
        grid_sync(nb);

        // ---- R2: dr = C2*(Zt + h@W2^T + b2 - Yt) (tf32, 128 u, 32x64) ----
        for (int u = bid; u < 128; u += nb) {
            int m0 = (u & 7) * 32, n0 = (u >> 3) * 64;
            float acc[1][2][4] = {};
            tile_mma<0, 32, 0>(g_h, g_W2, SM, H4, H4, m0, n0, 0, H4, acc);
#pragma unroll
            for (int nt = 0; nt < 2; nt++) {
                int m = m0 + wm * 16 + g;
                int nn = n0 + wn * 16 + nt * 8 + q * 2;
                float2 bb = *(const float2*)(g_b2 + nn);
                {
                    float2 zz = *(const float2*)(Zt + (size_t)m * HH + nn);
                    float2 yy = *(const float2*)(Yt + (size_t)m * HH + nn);
                    *(float2*)(g_dr + (size_t)m * HH + nn) = make_float2(
                        C2 * (zz.x + acc[0][nt][0] + bb.x - yy.x),
                        C2 * (zz.y + acc[0][nt][1] + bb.y - yy.y));
                }
                {
                    int m8 = m + 8;
                    float2 zz = *(const float2*)(Zt + (size_t)m8 * HH + nn);
                    float2 yy = *(const float2*)(Yt + (size_t)m8 * HH + nn);
                    *(float2*)(g_dr + (size_t)m8 * HH + nn) = make_float2(
                        C2 * (zz.x + acc[0][nt][2] + bb.x - yy.x),
                        C2 * (zz.y + acc[0][nt][3] + bb.y - yy.y));
                }
            }
        }
        grid_sync(nb);

        // ---- R3: da_pre partials = dr @ W2 (tf32 NN, 128 u, 64x64) ----
        for (int u = bid; u < 128; u += nb) {
            int sk = u & 7, tile = u >> 3;
            int m0 = (tile & 3) * 64, n0 = (tile >> 2) * 64;
            float acc[2][2][4] = {};
            tile_mma<1, 64, 0>(g_dr, g_W2, SM, HH, H4, m0, n0,
                               sk * 128, sk * 128 + 128, acc);
            float* cp = g_part + (size_t)sk * MN;
#pragma unroll
            for (int mt = 0; mt < 2; mt++)
#pragma unroll
                for (int nt = 0; nt < 2; nt++) {
                    int m = m0 + wm * 32 + mt * 16 + g;
                    int nn = n0 + wn * 16 + nt * 8 + q * 2;
                    *(float2*)(cp + (size_t)m * H4 + nn) =
                        make_float2(acc[mt][nt][0], acc[mt][nt][1]);
                    *(float2*)(cp + (size_t)(m + 8) * H4 + nn) =
                        make_float2(acc[mt][nt][2], acc[mt][nt][3]);
                }
        }
        grid_sync(nb);

        // ---- R4: da = sum(part) * gelu'(a) ----
        for (int idx = bid * 256 + tid; idx < MN; idx += nb * 256) {
            float s = 0.f;
#pragma unroll
            for (int z = 0; z < 8; z++) s += g_part[(size_t)z * MN + idx];
            g_da[idx] = s * gelu_grad(g_a[idx]);
        }
        grid_sync(nb);

        // ---- R5: weight updates (tf32 TN, 128 u, Kn=256) + biases ----
        for (int u = bid; u < 128; u += nb) {
            if (u < 64) {
                // W2[i,j] -= LR * sum_n dr[n,i] h[n,j]
                int i0 = (u & 15) * 64, j0 = (u >> 4) * 64;
                float acc[2][2][4] = {};
                tile_mma<2, 64, 0>(g_dr, g_h, SM, HH, H4, i0, j0, 0, NB, acc);
#pragma unroll
                for (int mt = 0; mt < 2; mt++)
#pragma unroll
                    for (int nt = 0; nt < 2; nt++) {
                        int i = i0 + wm * 32 + mt * 16 + g;
                        int j = j0 + wn * 16 + nt * 8 + q * 2;
                        float2* p0 = (float2*)(g_W2 + (size_t)i * H4 + j);
                        float2 o0 = *p0;
                        o0.x -= LR * acc[mt][nt][0]; o0.y -= LR * acc[mt][nt][1];
                        *p0 = o0;
                        float2* p1 = (float2*)(g_W2 + (size_t)(i + 8) * H4 + j);
                        float2 o1 = *p1;
                        o1.x -= LR * acc[mt][nt][2]; o1.y -= LR * acc[mt][nt][3];
                        *p1 = o1;
                    }
            } else {
                // W1[j,i] -= LR * sum_n da[n,j] Zt[n,i]
                int v = u - 64;
                int j0 = (v & 3) * 64, i0 = (v >> 2) * 64;
                float acc[2][2][4] = {};
                tile_mma<2, 64, 0>(g_da, Zt, SM, H4, DD, j0, i0, 0, NB, acc);
#pragma unroll
                for (int mt = 0; mt < 2; mt++)
#pragma unroll
                    for (int nt = 0; nt < 2; nt++) {
                        int j = j0 + wm * 32 + mt * 16 + g;
                        int i = i0 + wn * 16 + nt * 8 + q * 2;
                        float2* p0 = (float2*)(g_W1 + (size_t)j * DD + i);
                        float2 o0 = *p0;
                        o0.x -= LR * acc[mt][nt][0]; o0.y -= LR * acc[mt][nt][1];
                        *p0 = o0;
                        float2* p1 = (float2*)(g_W1 + (size_t)(j + 8) * DD + i);
                        float2 o1 = *p1;
                        o1.x -= LR * acc[mt][nt][2]; o1.y -= LR * acc[mt][nt][3];
                        *p1 = o1;
                    }
            }
        }
        // bias colsums (warp-parallel, no intra-block syncs)
        for (int c = gw; c < HH; c += nb * 8) {
            float s = 0.f;
            for (int n = lane; n < NB; n += 32) s += g_dr[(size_t)n * HH + c];
#pragma unroll
            for (int o = 16; o > 0; o >>= 1) s += __shfl_xor_sync(0xffffffffu, s, o);
            if (lane == 0) g_b2[c] -= LR * s;
        }
        for (int c = gw; c < H4; c += nb * 8) {
            float s = 0.f;
            for (int n = lane; n < NB; n += 32) s += g_da[(size_t)n * H4 + c];
#pragma unroll
            for (int o = 16; o > 0; o >>= 1) s += __shfl_xor_sync(0xffffffffu, s, o);
            if (lane == 0) g_b1[c] -= LR * s;
        }
        grid_sync(nb);

        // ---- R6: a2 partials = Qt @ W1_new^T (split-tf32, 128 u, 64x64) ----
        for (int u = bid; u < 128; u += nb) {
            int sk = u & 7, tile = u >> 3;
            int m0 = (tile & 3) * 64, n0 = (tile >> 2) * 64;
            float acc[2][2][4] = {};
            tile_mma<0, 64, 1>(Qt, g_W1, SM, DD, DD, m0, n0,
                               sk * 128, sk * 128 + 128, acc);
            float* cp = g_part + (size_t)sk * MN;
#pragma unroll
            for (int mt = 0; mt < 2; mt++)
#pragma unroll
                for (int nt = 0; nt < 2; nt++) {
                    int m = m0 + wm * 32 + mt * 16 + g;
                    int nn = n0 + wn * 16 + nt * 8 + q * 2;
                    *(float2*)(cp + (size_t)m * H4 + nn) =
                        make_float2(acc[mt][nt][0], acc[mt][nt][1]);
                    *(float2*)(cp + (size_t)(m + 8) * H4 + nn) =
                        make_float2(acc[mt][nt][2], acc[mt][nt][3]);
                }
        }
        grid_sync(nb);

        // ---- R7: h2 = gelu(sum(part) + b1_new) ----
        for (int idx = bid * 256 + tid; idx < MN; idx += nb * 256) {
            float s = 0.f;
#pragma unroll
            for (int z = 0; z < 8; z++) s += g_part[(size_t)z * MN + idx];
            s += g_b1[idx & (H4 - 1)];
            g_h2[idx] = gelu_f(s);
        }
        grid_sync(nb);
    }
}

// ---------------------------------------------------------------------------
// kernel_launch
// ---------------------------------------------------------------------------
extern "C" void kernel_launch(void* const* d_in, const int* in_sizes, int n_in,
                              void* d_out, int out_size)
{
    (void)in_sizes; (void)n_in; (void)out_size;
    const float* in_seq = (const float*)d_in[0];
    const float* t_k = (const float*)d_in[1];
    const float* t_v = (const float*)d_in[2];
    const float* t_q = (const float*)d_in[3];

    float *Z, *Y, *Q, *W1, *b1, *W2, *b2;
    cudaGetSymbolAddress((void**)&Z, g_Z);
    cudaGetSymbolAddress((void**)&Y, g_Y);
    cudaGetSymbolAddress((void**)&Q, g_Q);
    cudaGetSymbolAddress((void**)&W1, g_W1);
    cudaGetSymbolAddress((void**)&b1, g_b1);
    cudaGetSymbolAddress((void**)&W2, g_W2);
    cudaGetSymbolAddress((void**)&b2, g_b2);

    cudaMemcpyAsync(W1, d_in[4], sizeof(float) * H4 * HH, cudaMemcpyDeviceToDevice, 0);
    cudaMemcpyAsync(b1, d_in[5], sizeof(float) * H4, cudaMemcpyDeviceToDevice, 0);
    cudaMemcpyAsync(W2, d_in[6], sizeof(float) * HH * H4, cudaMemcpyDeviceToDevice, 0);
    cudaMemcpyAsync(b2, d_in[7], sizeof(float) * HH, cudaMemcpyDeviceToDevice, 0);

    // Phase A: tf32 tensor-core GEMMs
    const int M_big = T_ * NB;
    dim3 gA(M_big / 128, HH / 128);
    gemm_nt_tf32<<<gA, 256>>>(in_seq, t_k, Z, M_big, HH, DD);
    gemm_nt_tf32<<<gA, 256>>>(in_seq, t_v, Y, M_big, HH, DD);
    gemm_nt_tf32<<<gA, 256>>>(in_seq, t_q, Q, M_big, HH, DD);

    // Phase B: one persistent kernel, exactly one block per SM.
    int sms = 0;
    cudaDeviceGetAttribute(&sms, cudaDevAttrMultiProcessorCount, 0);
    if (sms <= 0 || sms > 148) sms = 148;
    ttt_persistent<<<sms, 256>>>((float*)d_out, sms);
}

// round 15
// speedup vs baseline: 1.0259x; 1.0259x over previous
#include <cuda_runtime.h>
#include <cuda_bf16.h>
#include <cstdint>
#include <cstddef>

// ---------------------------------------------------------------------------
// TTLinear. Phase A: 3 big tf32 tensor-core GEMMs. Phase B: one persistent
// kernel (256 thr/block, 1 block/SM), 128 steps, 8 regions (R10 structure).
// R15 = R10 + TREE BARRIER: the old single-counter grid_sync serialized 148
// same-address atomics (~2.5-4us/barrier x 1024 barriers ~= 3-4ms). Two-level
// tree (16 leaf counters on separate lines -> root -> gen) cuts the critical
// path to ~0.7us. Counters are monotonic: no resets, no races, replay-safe
// (baseline gen read at kernel entry).
// ---------------------------------------------------------------------------

constexpr int T_  = 128;
constexpr int NB  = 256;
constexpr int DD  = 1024;
constexpr int HH  = 1024;
constexpr int H4  = 256;
constexpr int NH  = NB * HH;    // 262144
constexpr int MN  = NB * H4;    // 65536
constexpr float LR = 1e-3f;
constexpr float C2 = 2.0f / (float)(NB * HH);

constexpr int SL   = 76;        // padded smem row stride
constexpr int SLAB = 16 * SL;

// ------------------------- device scratch ----------------------------------
__device__ float g_Z[(size_t)T_ * NH];
__device__ float g_Y[(size_t)T_ * NH];
__device__ float g_Q[(size_t)T_ * NH];
__device__ float g_W1[H4 * HH];
__device__ float g_b1[H4];
__device__ float g_W2[HH * H4];
__device__ float g_b2[HH];
__device__ float g_a[MN];
__device__ float g_h[MN];
__device__ float g_h2[MN];
__device__ float g_da[MN];
__device__ float g_dr[NB * HH];
__device__ float g_part[8 * MN];

// tree barrier state: 16 leaf counters on separate 128B lines + root + gen.
// ALL MONOTONIC (never reset) -> no reset/arrival races; replay-safe.
__device__ __align__(128) unsigned g_leaf[16 * 32];
__device__ __align__(128) unsigned g_root = 0;
__device__ __align__(128) unsigned g_gen = 0;

// ------------------------------ helpers ------------------------------------
__device__ __forceinline__ float gelu_f(float x) {
    return 0.5f * x * (1.0f + erff(x * 0.70710678118654752f));
}
__device__ __forceinline__ float gelu_grad(float x) {
    float cdf = 0.5f * (1.0f + erff(x * 0.70710678118654752f));
    float pdf = 0.3989422804014327f * expf(-0.5f * x * x);
    return cdf + x * pdf;
}
__device__ __forceinline__ float to_tf32(float x) {
    uint32_t u;
    asm("cvt.rna.tf32.f32 %0, %1;" : "=r"(u) : "f"(x));
    return __uint_as_float(u);
}
__device__ __forceinline__ void mma_tf32(float (&c)[4], const uint32_t (&a)[4],
                                         const uint32_t (&b)[2]) {
    asm volatile(
        "mma.sync.aligned.m16n8k8.row.col.f32.tf32.tf32.f32 "
        "{%0,%1,%2,%3}, {%4,%5,%6,%7}, {%8,%9}, {%0,%1,%2,%3};"
        : "+f"(c[0]), "+f"(c[1]), "+f"(c[2]), "+f"(c[3])
        : "r"(a[0]), "r"(a[1]), "r"(a[2]), "r"(a[3]), "r"(b[0]), "r"(b[1]));
}

// Two-level tree barrier. 'target' = gen0 + barrier_index (monotonic).
// Leaf l serves blocks with bid%16==l: for nb=148, leaves 0-3 have 10 blocks,
// leaves 4-15 have 9. Completion tests compare against monotonic totals.
// Bounded waiter spin: a sync bug degrades to wrong output, not a hang.
__device__ __forceinline__ void grid_sync_tree(unsigned nb, unsigned target) {
    __syncthreads();
    if (threadIdx.x == 0) {
        __threadfence();                               // release my writes
        const unsigned leaf = blockIdx.x & 15u;
        const unsigned cnt = (nb >> 4) + (leaf < (nb & 15u) ? 1u : 0u);
        if (atomicAdd(&g_leaf[leaf << 5], 1u) == target * cnt + cnt - 1u) {
            if (atomicAdd(&g_root, 1u) == target * 16u + 15u) {
                __threadfence();
                atomicAdd(&g_gen, 1u);                 // g_gen becomes target+1
            }
        }
        for (int spin = 0; spin < 2000000; spin++) {
            if (*(volatile unsigned*)&g_gen > target) break;
        }
        __threadfence();                               // acquire
    }
    __syncthreads();
}

// ---------------------------------------------------------------------------
// Phase A: C[M,N] = A[M,K] @ B[N,K]^T via tf32 mma.sync (unchanged, passing).
// ---------------------------------------------------------------------------
__global__ __launch_bounds__(256, 2) void gemm_nt_tf32(
    const float* __restrict__ A, const float* __restrict__ B,
    float* __restrict__ C, int M, int N, int K)
{
    __shared__ float As[2][16][136];
    __shared__ float Bs[2][16][136];
    const int m0 = blockIdx.x * 128, n0 = blockIdx.y * 128;
    const int tid = threadIdx.x;
    const int lrow = tid & 127, lc8 = (tid >> 7) * 8;
    const int w = tid >> 5, lane = tid & 31;
    const int wm = w >> 2, wn = w & 3;
    const int g = lane >> 2, q = lane & 3;

    float acc[4][4][4] = {};
    const float* Ag = A + (size_t)(m0 + lrow) * K + lc8;
    const float* Bg = B + (size_t)(n0 + lrow) * K + lc8;

    float4 ra0 = *(const float4*)(Ag);
    float4 ra1 = *(const float4*)(Ag + 4);
    float4 rb0 = *(const float4*)(Bg);
    float4 rb1 = *(const float4*)(Bg + 4);

    const int S = K / 16;
    for (int s = 0; s < S; s++) {
        const int buf = s & 1;
        {
            float* pa = &As[buf][lc8][lrow];
            pa[0*136] = to_tf32(ra0.x); pa[1*136] = to_tf32(ra0.y);
            pa[2*136] = to_tf32(ra0.z); pa[3*136] = to_tf32(ra0.w);
            pa[4*136] = to_tf32(ra1.x); pa[5*136] = to_tf32(ra1.y);
            pa[6*136] = to_tf32(ra1.z); pa[7*136] = to_tf32(ra1.w);
            float* pb = &Bs[buf][lc8][lrow];
            pb[0*136] = to_tf32(rb0.x); pb[1*136] = to_tf32(rb0.y);
            pb[2*136] = to_tf32(rb0.z); pb[3*136] = to_tf32(rb0.w);
            pb[4*136] = to_tf32(rb1.x); pb[5*136] = to_tf32(rb1.y);
            pb[6*136] = to_tf32(rb1.z); pb[7*136] = to_tf32(rb1.w);
        }
        if (s + 1 < S) {
            const float* a2 = Ag + (s + 1) * 16;
            const float* b2 = Bg + (s + 1) * 16;
            ra0 = *(const float4*)(a2);     ra1 = *(const float4*)(a2 + 4);
            rb0 = *(const float4*)(b2);     rb1 = *(const float4*)(b2 + 4);
        }
        __syncthreads();
#pragma unroll
        for (int kc = 0; kc < 16; kc += 8) {
            uint32_t af[4][4], bf[4][2];
#pragma unroll
            for (int mt = 0; mt < 4; mt++) {
                int r = wm * 64 + mt * 16 + g;
                af[mt][0] = __float_as_uint(As[buf][kc + q][r]);
                af[mt][1] = __float_as_uint(As[buf][kc + q][r + 8]);
                af[mt][2] = __float_as_uint(As[buf][kc + q + 4][r]);
                af[mt][3] = __float_as_uint(As[buf][kc + q + 4][r + 8]);
            }
#pragma unroll
            for (int nt = 0; nt < 4; nt++) {
                int c = wn * 32 + nt * 8 + g;
                bf[nt][0] = __float_as_uint(Bs[buf][kc + q][c]);
                bf[nt][1] = __float_as_uint(Bs[buf][kc + q + 4][c]);
            }
#pragma unroll
            for (int mt = 0; mt < 4; mt++)
#pragma unroll
                for (int nt = 0; nt < 4; nt++)
                    mma_tf32(acc[mt][nt], af[mt], bf[nt]);
        }
        __syncthreads();
    }
#pragma unroll
    for (int mt = 0; mt < 4; mt++)
#pragma unroll
        for (int nt = 0; nt < 4; nt++) {
            int r = m0 + wm * 64 + mt * 16 + g;
            int c = n0 + wn * 32 + nt * 8 + q * 2;
            *(float2*)&C[(size_t)r * N + c] =
                make_float2(acc[mt][nt][0], acc[mt][nt][1]);
            *(float2*)&C[(size_t)(r + 8) * N + c] =
                make_float2(acc[mt][nt][2], acc[mt][nt][3]);
        }
}

// ---------------------------------------------------------------------------
// Phase B tile machinery (identical to R10): k-major smem staging.
// MODE 0 NT: A[m,k],B[n,k]; MODE 1 NN: A[m,k],B[k,n]; MODE 2 TN: A[k,m],B[k,n]
// ---------------------------------------------------------------------------
template <int MODE, int TM>
struct Stage {
    float4 ra, rb; float2 ra2;
    __device__ __forceinline__ void fetch(const float* A, const float* B,
                                          int lda, int ldb, int m0, int n0, int k0,
                                          int tid) {
        if (MODE == 2) {
            ra = *(const float4*)(A + (size_t)(k0 + (tid >> 4)) * lda + m0 + (tid & 15) * 4);
        } else if (TM == 64) {
            ra = *(const float4*)(A + (size_t)(m0 + (tid >> 2)) * lda + k0 + (tid & 3) * 4);
        } else {
            ra2 = *(const float2*)(A + (size_t)(m0 + (tid >> 3)) * lda + k0 + (tid & 7) * 2);
        }
        if (MODE == 0) {
            rb = *(const float4*)(B + (size_t)(n0 + (tid >> 2)) * ldb + k0 + (tid & 3) * 4);
        } else {
            rb = *(const float4*)(B + (size_t)(k0 + (tid >> 4)) * ldb + n0 + (tid & 15) * 4);
        }
    }
    __device__ __forceinline__ void store(float* dA, float* dB, int tid) {
        if (MODE == 2) {
            *(float4*)(dA + (tid >> 4) * SL + (tid & 15) * 4) = ra;
        } else if (TM == 64) {
            int r = tid >> 2, c = (tid & 3) * 4;
            dA[(c + 0) * SL + r] = ra.x; dA[(c + 1) * SL + r] = ra.y;
            dA[(c + 2) * SL + r] = ra.z; dA[(c + 3) * SL + r] = ra.w;
        } else {
            int r = tid >> 3, c = (tid & 7) * 2;
            dA[(c + 0) * SL + r] = ra2.x; dA[(c + 1) * SL + r] = ra2.y;
        }
        if (MODE == 0) {
            int r = tid >> 2, c = (tid & 3) * 4;
            dB[(c + 0) * SL + r] = rb.x; dB[(c + 1) * SL + r] = rb.y;
            dB[(c + 2) * SL + r] = rb.z; dB[(c + 3) * SL + r] = rb.w;
        } else {
            *(float4*)(dB + (tid >> 4) * SL + (tid & 15) * 4) = rb;
        }
    }
};

// fp32 SIMT tile (exact; output path). TM=64: 4x4 micro; TM=32: 2x4 micro.
template <int MODE, int TM>
__device__ __forceinline__ void tile_f32(
    const float* __restrict__ A, const float* __restrict__ B, float* sm,
    int lda, int ldb, int m0, int n0, int kbeg, int kend,
    float (&acc)[4][4])
{
    const int tid = threadIdx.x;
    const int tx = tid & 15, ty = tid >> 4;
    float* smA = sm;
    float* smB = sm + 2 * SLAB;
    const int nslab = (kend - kbeg) >> 4;
    Stage<MODE, TM> st;

    st.fetch(A, B, lda, ldb, m0, n0, kbeg, tid);
    for (int s = 0; s < nslab; s++) {
        const int buf = s & 1;
        st.store(smA + buf * SLAB, smB + buf * SLAB, tid);
        if (s + 1 < nslab) st.fetch(A, B, lda, ldb, m0, n0, kbeg + (s + 1) * 16, tid);
        __syncthreads();
        const float* cA = smA + buf * SLAB;
        const float* cB = smB + buf * SLAB;
#pragma unroll
        for (int k = 0; k < 16; k++) {
            float4 b = *(const float4*)(cB + k * SL + tx * 4);
            if (TM == 64) {
                float4 a = *(const float4*)(cA + k * SL + ty * 4);
#pragma unroll
                for (int j = 0; j < 4; j++) {
                    float bj = (&b.x)[j];
                    acc[0][j] += a.x * bj; acc[1][j] += a.y * bj;
                    acc[2][j] += a.z * bj; acc[3][j] += a.w * bj;
                }
            } else {
                float2 a = *(const float2*)(cA + k * SL + ty * 2);
#pragma unroll
                for (int j = 0; j < 4; j++) {
                    float bj = (&b.x)[j];
                    acc[0][j] += a.x * bj; acc[1][j] += a.y * bj;
                }
            }
        }
        __syncthreads();
    }
}

// tf32 mma tile (gradient path). 8 warps = 2x4 grid, warp tile (TM/2)x16.
template <int MODE, int TM>
__device__ __forceinline__ void tile_mma(
    const float* __restrict__ A, const float* __restrict__ B, float* sm,
    int lda, int ldb, int m0, int n0, int kbeg, int kend,
    float (&acc)[TM / 32][2][4])
{
    const int tid = threadIdx.x;
    const int w = tid >> 5, lane = tid & 31;
    const int wm = w >> 2, wn = w & 3;
    const int g = lane >> 2, q = lane & 3;
    float* smA = sm;
    float* smB = sm + 2 * SLAB;
    const int nslab = (kend - kbeg) >> 4;
    Stage<MODE, TM> st;

    st.fetch(A, B, lda, ldb, m0, n0, kbeg, tid);
    for (int s = 0; s < nslab; s++) {
        const int buf = s & 1;
        st.store(smA + buf * SLAB, smB + buf * SLAB, tid);
        if (s + 1 < nslab) st.fetch(A, B, lda, ldb, m0, n0, kbeg + (s + 1) * 16, tid);
        __syncthreads();
        const float* cA = smA + buf * SLAB;
        const float* cB = smB + buf * SLAB;
#pragma unroll
        for (int kc = 0; kc < 16; kc += 8) {
            uint32_t af[TM / 32][4], bf[2][2];
#pragma unroll
            for (int mt = 0; mt < TM / 32; mt++) {
                int r = wm * (TM / 2) + mt * 16 + g;
                af[mt][0] = __float_as_uint(cA[(kc + q) * SL + r]);
                af[mt][1] = __float_as_uint(cA[(kc + q) * SL + r + 8]);
                af[mt][2] = __float_as_uint(cA[(kc + q + 4) * SL + r]);
                af[mt][3] = __float_as_uint(cA[(kc + q + 4) * SL + r + 8]);
            }
#pragma unroll
            for (int nt = 0; nt < 2; nt++) {
                int c = wn * 16 + nt * 8 + g;
                bf[nt][0] = __float_as_uint(cB[(kc + q) * SL + c]);
                bf[nt][1] = __float_as_uint(cB[(kc + q + 4) * SL + c]);
            }
#pragma unroll
            for (int mt = 0; mt < TM / 32; mt++)
#pragma unroll
                for (int nt = 0; nt < 2; nt++)
                    mma_tf32(acc[mt][nt], af[mt], bf[nt]);
        }
        __syncthreads();
    }
}

// ---------------------------------------------------------------------------
// Persistent Phase B kernel: 256 threads/block, one tile-unit per block/wave.
// Regions identical to R10; only the barrier changed.
// ---------------------------------------------------------------------------
__global__ __launch_bounds__(256, 1) void ttt_persistent(float* __restrict__ out,
                                                         int nb)
{
    __shared__ __align__(16) float SM[4 * SLAB];
    __shared__ unsigned s_gen0;
    const int bid = blockIdx.x, tid = threadIdx.x;
    const int tx = tid & 15, ty = tid >> 4;
    const int w = tid >> 5, lane = tid & 31;
    const int wm = w >> 2, wn = w & 3;
    const int g = lane >> 2, q = lane & 3;
    const int gw = (bid * 256 + tid) >> 5;

    if (tid == 0) s_gen0 = *(volatile unsigned*)&g_gen;   // replay-safe baseline
    __syncthreads();
    unsigned barno = 0;

    for (int step = 0; step <= T_; step++) {
        // ---- R0: S10 of step-1 (fp32 exact) + S1 partials (tf32 mma) ----
        {
            const int nA = (step > 0) ? 128 : 0;
            const int nTot = nA + ((step < T_) ? 128 : 0);
            for (int u = bid; u < nTot; u += nb) {
                const int uu = (step > 0) ? u : u + 128;
                if (uu < 128) {
                    const int t = step - 1;
                    const float* Qt = g_Q + (size_t)t * NH;
                    float* od = out + (size_t)t * NH;
                    int m0 = (uu & 7) * 32, n0 = (uu >> 3) * 64;
                    float acc[4][4] = {};
                    tile_f32<0, 32>(g_h2, g_W2, SM, H4, H4, m0, n0, 0, H4, acc);
                    int n = n0 + tx * 4;
                    float4 bb = *(const float4*)(g_b2 + n);
#pragma unroll
                    for (int r = 0; r < 2; r++) {
                        int m = m0 + ty * 2 + r;
                        float4 qv = *(const float4*)(Qt + (size_t)m * HH + n);
                        *(float4*)(od + (size_t)m * HH + n) = make_float4(
                            qv.x + acc[r][0] + bb.x, qv.y + acc[r][1] + bb.y,
                            qv.z + acc[r][2] + bb.z, qv.w + acc[r][3] + bb.w);
                    }
                } else {
                    const int v = uu - 128;
                    const float* Zt = g_Z + (size_t)step * NH;
                    int sk = v & 7, tile = v >> 3;
                    int m0 = (tile & 3) * 64, n0 = (tile >> 2) * 64;
                    float acc[2][2][4] = {};
                    tile_mma<0, 64>(Zt, g_W1, SM, DD, DD, m0, n0,
                                    sk * 128, sk * 128 + 128, acc);
                    float* cp = g_part + (size_t)sk * MN;
#pragma unroll
                    for (int mt = 0; mt < 2; mt++)
#pragma unroll
                        for (int nt = 0; nt < 2; nt++) {
                            int m = m0 + wm * 32 + mt * 16 + g;
                            int nn = n0 + wn * 16 + nt * 8 + q * 2;
                            *(float2*)(cp + (size_t)m * H4 + nn) =
                                make_float2(acc[mt][nt][0], acc[mt][nt][1]);
                            *(float2*)(cp + (size_t)(m + 8) * H4 + nn) =
                                make_float2(acc[mt][nt][2], acc[mt][nt][3]);
                        }
                }
            }
        }
        grid_sync_tree(nb, s_gen0 + barno); ++barno;
        if (step == T_) break;

        const int t = step;
        const float* Zt = g_Z + (size_t)t * NH;
        const float* Yt = g_Y + (size_t)t * NH;
        const float* Qt = g_Q + (size_t)t * NH;

        // ---- R1: a = sum(part)+b1; h = gelu(a) ----
        for (int idx = bid * 256 + tid; idx < MN; idx += nb * 256) {
            float s = 0.f;
#pragma unroll
            for (int z = 0; z < 8; z++) s += g_part[(size_t)z * MN + idx];
            s += g_b1[idx & (H4 - 1)];
            g_a[idx] = s;
            g_h[idx] = gelu_f(s);
        }
        grid_sync_tree(nb, s_gen0 + barno); ++barno;

        // ---- R2: dr = C2*(Zt + h@W2^T + b2 - Yt) (tf32 mma, 32x64) ----
        for (int u = bid; u < 128; u += nb) {
            int m0 = (u & 7) * 32, n0 = (u >> 3) * 64;
            float acc[1][2][4] = {};
            tile_mma<0, 32>(g_h, g_W2, SM, H4, H4, m0, n0, 0, H4, acc);
#pragma unroll
            for (int nt = 0; nt < 2; nt++) {
                int m = m0 + wm * 16 + g;
                int nn = n0 + wn * 16 + nt * 8 + q * 2;
                float2 bb = *(const float2*)(g_b2 + nn);
                {
                    float2 zz = *(const float2*)(Zt + (size_t)m * HH + nn);
                    float2 yy = *(const float2*)(Yt + (size_t)m * HH + nn);
                    *(float2*)(g_dr + (size_t)m * HH + nn) = make_float2(
                        C2 * (zz.x + acc[0][nt][0] + bb.x - yy.x),
                        C2 * (zz.y + acc[0][nt][1] + bb.y - yy.y));
                }
                {
                    int m8 = m + 8;
                    float2 zz = *(const float2*)(Zt + (size_t)m8 * HH + nn);
                    float2 yy = *(const float2*)(Yt + (size_t)m8 * HH + nn);
                    *(float2*)(g_dr + (size_t)m8 * HH + nn) = make_float2(
                        C2 * (zz.x + acc[0][nt][2] + bb.x - yy.x),
                        C2 * (zz.y + acc[0][nt][3] + bb.y - yy.y));
                }
            }
        }
        grid_sync_tree(nb, s_gen0 + barno); ++barno;

        // ---- R3: da_pre partials = dr @ W2 (tf32 mma NN, 64x64) ----
        for (int u = bid; u < 128; u += nb) {
            int sk = u & 7, tile = u >> 3;
            int m0 = (tile & 3) * 64, n0 = (tile >> 2) * 64;
            float acc[2][2][4] = {};
            tile_mma<1, 64>(g_dr, g_W2, SM, HH, H4, m0, n0,
                            sk * 128, sk * 128 + 128, acc);
            float* cp = g_part + (size_t)sk * MN;
#pragma unroll
            for (int mt = 0; mt < 2; mt++)
#pragma unroll
                for (int nt = 0; nt < 2; nt++) {
                    int m = m0 + wm * 32 + mt * 16 + g;
                    int nn = n0 + wn * 16 + nt * 8 + q * 2;
                    *(float2*)(cp + (size_t)m * H4 + nn) =
                        make_float2(acc[mt][nt][0], acc[mt][nt][1]);
                    *(float2*)(cp + (size_t)(m + 8) * H4 + nn) =
                        make_float2(acc[mt][nt][2], acc[mt][nt][3]);
                }
        }
        grid_sync_tree(nb, s_gen0 + barno); ++barno;

        // ---- R4: da = sum(part) * gelu'(a) ----
        for (int idx = bid * 256 + tid; idx < MN; idx += nb * 256) {
            float s = 0.f;
#pragma unroll
            for (int z = 0; z < 8; z++) s += g_part[(size_t)z * MN + idx];
            g_da[idx] = s * gelu_grad(g_a[idx]);
        }
        grid_sync_tree(nb, s_gen0 + barno); ++barno;

        // ---- R5: weight updates (tf32 mma TN, Kn=256) + biases ----
        for (int u = bid; u < 128; u += nb) {
            if (u < 64) {
                int i0 = (u & 15) * 64, j0 = (u >> 4) * 64;
                float acc[2][2][4] = {};
                tile_mma<2, 64>(g_dr, g_h, SM, HH, H4, i0, j0, 0, NB, acc);
#pragma unroll
                for (int mt = 0; mt < 2; mt++)
#pragma unroll
                    for (int nt = 0; nt < 2; nt++) {
                        int i = i0 + wm * 32 + mt * 16 + g;
                        int j = j0 + wn * 16 + nt * 8 + q * 2;
                        float2* p0 = (float2*)(g_W2 + (size_t)i * H4 + j);
                        float2 o0 = *p0;
                        o0.x -= LR * acc[mt][nt][0]; o0.y -= LR * acc[mt][nt][1];
                        *p0 = o0;
                        float2* p1 = (float2*)(g_W2 + (size_t)(i + 8) * H4 + j);
                        float2 o1 = *p1;
                        o1.x -= LR * acc[mt][nt][2]; o1.y -= LR * acc[mt][nt][3];
                        *p1 = o1;
                    }
            } else {
                int v = u - 64;
                int j0 = (v & 3) * 64, i0 = (v >> 2) * 64;
                float acc[2][2][4] = {};
                tile_mma<2, 64>(g_da, Zt, SM, H4, DD, j0, i0, 0, NB, acc);
#pragma unroll
                for (int mt = 0; mt < 2; mt++)
#pragma unroll
                    for (int nt = 0; nt < 2; nt++) {
                        int j = j0 + wm * 32 + mt * 16 + g;
                        int i = i0 + wn * 16 + nt * 8 + q * 2;
                        float2* p0 = (float2*)(g_W1 + (size_t)j * DD + i);
                        float2 o0 = *p0;
                        o0.x -= LR * acc[mt][nt][0]; o0.y -= LR * acc[mt][nt][1];
                        *p0 = o0;
                        float2* p1 = (float2*)(g_W1 + (size_t)(j + 8) * DD + i);
                        float2 o1 = *p1;
                        o1.x -= LR * acc[mt][nt][2]; o1.y -= LR * acc[mt][nt][3];
                        *p1 = o1;
                    }
            }
        }
        // bias colsums (warp-parallel, no intra-block syncs)
        for (int c = gw; c < HH; c += nb * 8) {
            float s = 0.f;
            for (int n = lane; n < NB; n += 32) s += g_dr[(size_t)n * HH + c];
#pragma unroll
            for (int o = 16; o > 0; o >>= 1) s += __shfl_xor_sync(0xffffffffu, s, o);
            if (lane == 0) g_b2[c] -= LR * s;
        }
        for (int c = gw; c < H4; c += nb * 8) {
            float s = 0.f;
            for (int n = lane; n < NB; n += 32) s += g_da[(size_t)n * H4 + c];
#pragma unroll
            for (int o = 16; o > 0; o >>= 1) s += __shfl_xor_sync(0xffffffffu, s, o);
            if (lane == 0) g_b1[c] -= LR * s;
        }
        grid_sync_tree(nb, s_gen0 + barno); ++barno;

        // ---- R6: a2 partials = Qt @ W1_new^T (EXACT fp32, 64x64) ----
        for (int u = bid; u < 128; u += nb) {
            int sk = u & 7, tile = u >> 3;
            int m0 = (tile & 3) * 64, n0 = (tile >> 2) * 64;
            float acc[4][4] = {};
            tile_f32<0, 64>(Qt, g_W1, SM, DD, DD, m0, n0,
                            sk * 128, sk * 128 + 128, acc);
            float* cp = g_part + (size_t)sk * MN;
#pragma unroll
            for (int r = 0; r < 4; r++)
                *(float4*)(cp + (size_t)(m0 + ty * 4 + r) * H4 + n0 + tx * 4) =
                    make_float4(acc[r][0], acc[r][1], acc[r][2], acc[r][3]);
        }
        grid_sync_tree(nb, s_gen0 + barno); ++barno;

        // ---- R7: h2 = gelu(sum(part) + b1_new) ----
        for (int idx = bid * 256 + tid; idx < MN; idx += nb * 256) {
            float s = 0.f;
#pragma unroll
            for (int z = 0; z < 8; z++) s += g_part[(size_t)z * MN + idx];
            s += g_b1[idx & (H4 - 1)];
            g_h2[idx] = gelu_f(s);
        }
        grid_sync_tree(nb, s_gen0 + barno); ++barno;
    }
}

// ---------------------------------------------------------------------------
// kernel_launch
// ---------------------------------------------------------------------------
extern "C" void kernel_launch(void* const* d_in, const int* in_sizes, int n_in,
                              void* d_out, int out_size)
{
    (void)in_sizes; (void)n_in; (void)out_size;
    const float* in_seq = (const float*)d_in[0];
    const float* t_k = (const float*)d_in[1];
    const float* t_v = (const float*)d_in[2];
    const float* t_q = (const float*)d_in[3];

    float *Z, *Y, *Q, *W1, *b1, *W2, *b2;
    cudaGetSymbolAddress((void**)&Z, g_Z);
    cudaGetSymbolAddress((void**)&Y, g_Y);
    cudaGetSymbolAddress((void**)&Q, g_Q);
    cudaGetSymbolAddress((void**)&W1, g_W1);
    cudaGetSymbolAddress((void**)&b1, g_b1);
    cudaGetSymbolAddress((void**)&W2, g_W2);
    cudaGetSymbolAddress((void**)&b2, g_b2);

    cudaMemcpyAsync(W1, d_in[4], sizeof(float) * H4 * HH, cudaMemcpyDeviceToDevice, 0);
    cudaMemcpyAsync(b1, d_in[5], sizeof(float) * H4, cudaMemcpyDeviceToDevice, 0);
    cudaMemcpyAsync(W2, d_in[6], sizeof(float) * HH * H4, cudaMemcpyDeviceToDevice, 0);
    cudaMemcpyAsync(b2, d_in[7], sizeof(float) * HH, cudaMemcpyDeviceToDevice, 0);

    // Phase A: tf32 tensor-core GEMMs
    const int M_big = T_ * NB;
    dim3 gA(M_big / 128, HH / 128);
    gemm_nt_tf32<<<gA, 256>>>(in_seq, t_k, Z, M_big, HH, DD);
    gemm_nt_tf32<<<gA, 256>>>(in_seq, t_v, Y, M_big, HH, DD);
    gemm_nt_tf32<<<gA, 256>>>(in_seq, t_q, Q, M_big, HH, DD);

    // Phase B: one persistent kernel, exactly one block per SM.
    int sms = 0;
    cudaDeviceGetAttribute(&sms, cudaDevAttrMultiProcessorCount, 0);
    if (sms <= 0 || sms > 148) sms = 148;
    ttt_persistent<<<sms, 256>>>((float*)d_out, sms);
}

// round 16
// speedup vs baseline: 1.1830x; 1.1531x over previous
#include <cuda_runtime.h>
#include <cuda_bf16.h>
#include <cstdint>
#include <cstddef>

// ---------------------------------------------------------------------------
// TTLinear. Phase A: 3 big tf32 tensor-core GEMMs. Phase B: one persistent
// kernel (256 thr/block, 1 block/SM), 128 steps, 8 regions (R10 structure,
// single-counter barrier). R16: every Phase-B tile uses a 4-STAGE cp.async
// PIPELINE (3 slabs always in flight) -> the per-slab exposed L2 latency that
// bounded R10..R15 (~400-500cyc/slab) collapses to max(compute, issue).
// Smem layouts are native-major with conflict-free pad strides. Output-path
// tiles (S10, R6) use 3-mma split-tf32; gradient tiles plain tf32.
// ---------------------------------------------------------------------------

constexpr int T_  = 128;
constexpr int NB  = 256;
constexpr int DD  = 1024;
constexpr int HH  = 1024;
constexpr int H4  = 256;
constexpr int NH  = NB * HH;    // 262144
constexpr int MN  = NB * H4;    // 65536
constexpr float LR = 1e-3f;
constexpr float C2 = 2.0f / (float)(NB * HH);

constexpr int SMM = 20;         // m-major smem row stride (16 k + 4 pad)
constexpr int SKM = 72;         // k-major smem row stride (64 + 8 pad)
constexpr int STG_FL = 2560;    // floats per stage (A at 0, B at 1280)
// 4 stages x 2560 floats = 40KB smem

// ------------------------- device scratch ----------------------------------
__device__ float g_Z[(size_t)T_ * NH];
__device__ float g_Y[(size_t)T_ * NH];
__device__ float g_Q[(size_t)T_ * NH];
__device__ float g_W1[H4 * HH];
__device__ float g_b1[H4];
__device__ float g_W2[HH * H4];
__device__ float g_b2[HH];
__device__ float g_a[MN];
__device__ float g_h[MN];
__device__ float g_h2[MN];
__device__ float g_da[MN];
__device__ float g_dr[NB * HH];
__device__ float g_part[8 * MN];

__device__ __align__(128) unsigned g_cnt = 0;
__device__ __align__(128) unsigned g_gen = 0;

// ------------------------------ helpers ------------------------------------
__device__ __forceinline__ float gelu_f(float x) {
    return 0.5f * x * (1.0f + erff(x * 0.70710678118654752f));
}
__device__ __forceinline__ float gelu_grad(float x) {
    float cdf = 0.5f * (1.0f + erff(x * 0.70710678118654752f));
    float pdf = 0.3989422804014327f * expf(-0.5f * x * x);
    return cdf + x * pdf;
}
__device__ __forceinline__ float to_tf32(float x) {
    uint32_t u;
    asm("cvt.rna.tf32.f32 %0, %1;" : "=r"(u) : "f"(x));
    return __uint_as_float(u);
}
__device__ __forceinline__ void mma_tf32(float (&c)[4], const uint32_t (&a)[4],
                                         const uint32_t (&b)[2]) {
    asm volatile(
        "mma.sync.aligned.m16n8k8.row.col.f32.tf32.tf32.f32 "
        "{%0,%1,%2,%3}, {%4,%5,%6,%7}, {%8,%9}, {%0,%1,%2,%3};"
        : "+f"(c[0]), "+f"(c[1]), "+f"(c[2]), "+f"(c[3])
        : "r"(a[0]), "r"(a[1]), "r"(a[2]), "r"(a[3]), "r"(b[0]), "r"(b[1]));
}
__device__ __forceinline__ void cp16(unsigned dst, const void* src) {
    asm volatile("cp.async.cg.shared.global [%0], [%1], 16;" :: "r"(dst), "l"(src));
}
__device__ __forceinline__ void cp_commit() {
    asm volatile("cp.async.commit_group;");
}
template <int N>
__device__ __forceinline__ void cp_wait() {
    asm volatile("cp.async.wait_group %0;" :: "n"(N));
}

// Hot-spin grid barrier, bounded (sync bug -> wrong output, not a hang).
__device__ __forceinline__ void grid_sync(unsigned nb) {
    __syncthreads();
    if (threadIdx.x == 0) {
        unsigned gen = *(volatile unsigned*)&g_gen;
        __threadfence();
        if (atomicAdd(&g_cnt, 1) == nb - 1) {
            g_cnt = 0;
            __threadfence();
            atomicAdd(&g_gen, 1);
        } else {
            for (int spin = 0; spin < 1000000; spin++) {
                if (*(volatile unsigned*)&g_gen != gen) break;
            }
        }
        __threadfence();
    }
    __syncthreads();
}

// ---------------------------------------------------------------------------
// Phase A: C[M,N] = A[M,K] @ B[N,K]^T via tf32 mma.sync (unchanged, passing).
// ---------------------------------------------------------------------------
__global__ __launch_bounds__(256, 2) void gemm_nt_tf32(
    const float* __restrict__ A, const float* __restrict__ B,
    float* __restrict__ C, int M, int N, int K)
{
    __shared__ float As[2][16][136];
    __shared__ float Bs[2][16][136];
    const int m0 = blockIdx.x * 128, n0 = blockIdx.y * 128;
    const int tid = threadIdx.x;
    const int lrow = tid & 127, lc8 = (tid >> 7) * 8;
    const int w = tid >> 5, lane = tid & 31;
    const int wm = w >> 2, wn = w & 3;
    const int g = lane >> 2, q = lane & 3;

    float acc[4][4][4] = {};
    const float* Ag = A + (size_t)(m0 + lrow) * K + lc8;
    const float* Bg = B + (size_t)(n0 + lrow) * K + lc8;

    float4 ra0 = *(const float4*)(Ag);
    float4 ra1 = *(const float4*)(Ag + 4);
    float4 rb0 = *(const float4*)(Bg);
    float4 rb1 = *(const float4*)(Bg + 4);

    const int S = K / 16;
    for (int s = 0; s < S; s++) {
        const int buf = s & 1;
        {
            float* pa = &As[buf][lc8][lrow];
            pa[0*136] = to_tf32(ra0.x); pa[1*136] = to_tf32(ra0.y);
            pa[2*136] = to_tf32(ra0.z); pa[3*136] = to_tf32(ra0.w);
            pa[4*136] = to_tf32(ra1.x); pa[5*136] = to_tf32(ra1.y);
            pa[6*136] = to_tf32(ra1.z); pa[7*136] = to_tf32(ra1.w);
            float* pb = &Bs[buf][lc8][lrow];
            pb[0*136] = to_tf32(rb0.x); pb[1*136] = to_tf32(rb0.y);
            pb[2*136] = to_tf32(rb0.z); pb[3*136] = to_tf32(rb0.w);
            pb[4*136] = to_tf32(rb1.x); pb[5*136] = to_tf32(rb1.y);
            pb[6*136] = to_tf32(rb1.z); pb[7*136] = to_tf32(rb1.w);
        }
        if (s + 1 < S) {
            const float* a2 = Ag + (s + 1) * 16;
            const float* b2 = Bg + (s + 1) * 16;
            ra0 = *(const float4*)(a2);     ra1 = *(const float4*)(a2 + 4);
            rb0 = *(const float4*)(b2);     rb1 = *(const float4*)(b2 + 4);
        }
        __syncthreads();
#pragma unroll
        for (int kc = 0; kc < 16; kc += 8) {
            uint32_t af[4][4], bf[4][2];
#pragma unroll
            for (int mt = 0; mt < 4; mt++) {
                int r = wm * 64 + mt * 16 + g;
                af[mt][0] = __float_as_uint(As[buf][kc + q][r]);
                af[mt][1] = __float_as_uint(As[buf][kc + q][r + 8]);
                af[mt][2] = __float_as_uint(As[buf][kc + q + 4][r]);
                af[mt][3] = __float_as_uint(As[buf][kc + q + 4][r + 8]);
            }
#pragma unroll
            for (int nt = 0; nt < 4; nt++) {
                int c = wn * 32 + nt * 8 + g;
                bf[nt][0] = __float_as_uint(Bs[buf][kc + q][c]);
                bf[nt][1] = __float_as_uint(Bs[buf][kc + q + 4][c]);
            }
#pragma unroll
            for (int mt = 0; mt < 4; mt++)
#pragma unroll
                for (int nt = 0; nt < 4; nt++)
                    mma_tf32(acc[mt][nt], af[mt], bf[nt]);
        }
        __syncthreads();
    }
#pragma unroll
    for (int mt = 0; mt < 4; mt++)
#pragma unroll
        for (int nt = 0; nt < 4; nt++) {
            int r = m0 + wm * 64 + mt * 16 + g;
            int c = n0 + wn * 32 + nt * 8 + q * 2;
            *(float2*)&C[(size_t)r * N + c] =
                make_float2(acc[mt][nt][0], acc[mt][nt][1]);
            *(float2*)&C[(size_t)(r + 8) * N + c] =
                make_float2(acc[mt][nt][2], acc[mt][nt][3]);
        }
}

// ---------------------------------------------------------------------------
// cp.async slab issue for one 16-k slab into stage 'st'.
// MODE 0 NT: A[m,k],B[n,k]; MODE 1 NN: A[m,k],B[k,n]; MODE 2 TN: A[k,m],B[k,n]
// smem: A m-major [rows][20] or k-major [16][72]; B n-major [64][20] or
// k-major [16][72]. All cp16 destinations 16B-aligned.
// ---------------------------------------------------------------------------
template <int MODE, int TM>
__device__ __forceinline__ void issue_slab(
    const float* __restrict__ A, const float* __restrict__ B, unsigned smu,
    int lda, int ldb, int m0, int n0, int k0, int st, int tid)
{
    unsigned sa = smu + (unsigned)(st * STG_FL) * 4u;
    unsigned sb = sa + 1280u * 4u;
    if (MODE == 2) {
        int k = tid >> 4, m4 = (tid & 15) * 4;
        cp16(sa + (unsigned)(k * SKM + m4) * 4u,
             A + (size_t)(k0 + k) * lda + m0 + m4);
    } else if (TM == 64) {
        int r = tid >> 2, c4 = (tid & 3) * 4;
        cp16(sa + (unsigned)(r * SMM + c4) * 4u,
             A + (size_t)(m0 + r) * lda + k0 + c4);
    } else {
        if (tid < 128) {
            int r = tid >> 2, c4 = (tid & 3) * 4;
            cp16(sa + (unsigned)(r * SMM + c4) * 4u,
                 A + (size_t)(m0 + r) * lda + k0 + c4);
        }
    }
    if (MODE == 0) {
        int r = tid >> 2, c4 = (tid & 3) * 4;
        cp16(sb + (unsigned)(r * SMM + c4) * 4u,
             B + (size_t)(n0 + r) * ldb + k0 + c4);
    } else {
        int k = tid >> 4, n4 = (tid & 15) * 4;
        cp16(sb + (unsigned)(k * SKM + n4) * 4u,
             B + (size_t)(k0 + k) * ldb + n0 + n4);
    }
    cp_commit();
}

// ---------------------------------------------------------------------------
// Phase B tile: TM x 64, tf32 mma, 4-stage cp.async pipeline.
// SPLIT 0: plain tf32; 1: 3-mma split-tf32 (near-fp32 output path).
// Fragment banks: m-major g*20+q and k-major q*8+g are both conflict-free.
// nslab is 8 or 16 (multiple of 4) -> stage reuse across tiles is race-free.
// ---------------------------------------------------------------------------
template <int MODE, int TM, int SPLIT>
__device__ __forceinline__ void tile_cp(
    const float* __restrict__ A, const float* __restrict__ B,
    float* sm, unsigned smu,
    int lda, int ldb, int m0, int n0, int kbeg, int kend,
    float (&acc)[TM / 32][2][4])
{
    const int tid = threadIdx.x;
    const int w = tid >> 5, lane = tid & 31;
    const int wm = w >> 2, wn = w & 3;
    const int g = lane >> 2, q = lane & 3;
    const int nslab = (kend - kbeg) >> 4;

#pragma unroll
    for (int s = 0; s < 3; s++)
        issue_slab<MODE, TM>(A, B, smu, lda, ldb, m0, n0, kbeg + s * 16, s, tid);

    for (int s = 0; s < nslab; s++) {
        const int st = s & 3;
        const int rem = nslab - s;
        if (rem > 2)      cp_wait<2>();
        else if (rem == 2) cp_wait<1>();
        else               cp_wait<0>();
        __syncthreads();
        if (s + 3 < nslab)
            issue_slab<MODE, TM>(A, B, smu, lda, ldb, m0, n0,
                                 kbeg + (s + 3) * 16, (s + 3) & 3, tid);
        const float* cA = sm + st * STG_FL;
        const float* cB = sm + st * STG_FL + 1280;
#pragma unroll
        for (int kc = 0; kc < 16; kc += 8) {
            float a0[TM / 32], a1[TM / 32], a2[TM / 32], a3[TM / 32];
#pragma unroll
            for (int mt = 0; mt < TM / 32; mt++) {
                int r = wm * (TM / 2) + mt * 16 + g;
                if (MODE == 2) {
                    a0[mt] = cA[(kc + q) * SKM + r];
                    a1[mt] = cA[(kc + q) * SKM + r + 8];
                    a2[mt] = cA[(kc + q + 4) * SKM + r];
                    a3[mt] = cA[(kc + q + 4) * SKM + r + 8];
                } else {
                    a0[mt] = cA[r * SMM + kc + q];
                    a1[mt] = cA[(r + 8) * SMM + kc + q];
                    a2[mt] = cA[r * SMM + kc + q + 4];
                    a3[mt] = cA[(r + 8) * SMM + kc + q + 4];
                }
            }
            float b0[2], b1[2];
#pragma unroll
            for (int nt = 0; nt < 2; nt++) {
                int c = wn * 16 + nt * 8 + g;
                if (MODE == 0) {
                    b0[nt] = cB[c * SMM + kc + q];
                    b1[nt] = cB[c * SMM + kc + q + 4];
                } else {
                    b0[nt] = cB[(kc + q) * SKM + c];
                    b1[nt] = cB[(kc + q + 4) * SKM + c];
                }
            }
            if (SPLIT == 0) {
#pragma unroll
                for (int mt = 0; mt < TM / 32; mt++) {
                    uint32_t af[4] = {__float_as_uint(a0[mt]), __float_as_uint(a1[mt]),
                                      __float_as_uint(a2[mt]), __float_as_uint(a3[mt])};
#pragma unroll
                    for (int nt = 0; nt < 2; nt++) {
                        uint32_t bf[2] = {__float_as_uint(b0[nt]), __float_as_uint(b1[nt])};
                        mma_tf32(acc[mt][nt], af, bf);
                    }
                }
            } else {
#pragma unroll
                for (int mt = 0; mt < TM / 32; mt++) {
                    float h0 = to_tf32(a0[mt]), h1 = to_tf32(a1[mt]);
                    float h2 = to_tf32(a2[mt]), h3 = to_tf32(a3[mt]);
                    uint32_t afh[4] = {__float_as_uint(h0), __float_as_uint(h1),
                                       __float_as_uint(h2), __float_as_uint(h3)};
                    uint32_t afl[4] = {__float_as_uint(to_tf32(a0[mt] - h0)),
                                       __float_as_uint(to_tf32(a1[mt] - h1)),
                                       __float_as_uint(to_tf32(a2[mt] - h2)),
                                       __float_as_uint(to_tf32(a3[mt] - h3))};
#pragma unroll
                    for (int nt = 0; nt < 2; nt++) {
                        float g0 = to_tf32(b0[nt]), g1 = to_tf32(b1[nt]);
                        uint32_t bfh[2] = {__float_as_uint(g0), __float_as_uint(g1)};
                        uint32_t bfl[2] = {__float_as_uint(to_tf32(b0[nt] - g0)),
                                           __float_as_uint(to_tf32(b1[nt] - g1))};
                        mma_tf32(acc[mt][nt], afh, bfh);
                        mma_tf32(acc[mt][nt], afl, bfh);
                        mma_tf32(acc[mt][nt], afh, bfl);
                    }
                }
            }
        }
    }
    __syncthreads();   // all readers done before caller reuses stages
}

// ---------------------------------------------------------------------------
// Persistent Phase B kernel: 256 threads/block, one tile-unit per block/wave.
// Regions identical to R10; tiles now cp.async-pipelined.
// ---------------------------------------------------------------------------
__global__ __launch_bounds__(256, 1) void ttt_persistent(float* __restrict__ out,
                                                         int nb)
{
    __shared__ __align__(16) float SM[4 * STG_FL];
    const unsigned smu = (unsigned)__cvta_generic_to_shared(SM);
    const int bid = blockIdx.x, tid = threadIdx.x;
    const int w = tid >> 5, lane = tid & 31;
    const int wm = w >> 2, wn = w & 3;
    const int g = lane >> 2, q = lane & 3;
    const int gw = (bid * 256 + tid) >> 5;

    for (int step = 0; step <= T_; step++) {
        // ---- R0: S10 of step-1 (split-tf32, 128 u, 32x64, K=256)
        //        + S1 partials of step (tf32, 128 u, 64x64, K=128) ----
        {
            const int nA = (step > 0) ? 128 : 0;
            const int nTot = nA + ((step < T_) ? 128 : 0);
            for (int u = bid; u < nTot; u += nb) {
                const int uu = (step > 0) ? u : u + 128;
                if (uu < 128) {
                    const int t = step - 1;
                    const float* Qt = g_Q + (size_t)t * NH;
                    float* od = out + (size_t)t * NH;
                    int m0 = (uu & 7) * 32, n0 = (uu >> 3) * 64;
                    float acc[1][2][4] = {};
                    tile_cp<0, 32, 1>(g_h2, g_W2, SM, smu, H4, H4, m0, n0, 0, H4, acc);
#pragma unroll
                    for (int nt = 0; nt < 2; nt++) {
                        int m = m0 + wm * 16 + g;
                        int nn = n0 + wn * 16 + nt * 8 + q * 2;
                        float2 bb = *(const float2*)(g_b2 + nn);
                        {
                            float2 qv = *(const float2*)(Qt + (size_t)m * HH + nn);
                            *(float2*)(od + (size_t)m * HH + nn) = make_float2(
                                qv.x + acc[0][nt][0] + bb.x,
                                qv.y + acc[0][nt][1] + bb.y);
                        }
                        {
                            int m8 = m + 8;
                            float2 qv = *(const float2*)(Qt + (size_t)m8 * HH + nn);
                            *(float2*)(od + (size_t)m8 * HH + nn) = make_float2(
                                qv.x + acc[0][nt][2] + bb.x,
                                qv.y + acc[0][nt][3] + bb.y);
                        }
                    }
                } else {
                    const int v = uu - 128;
                    const float* Zt = g_Z + (size_t)step * NH;
                    int sk = v & 7, tile = v >> 3;
                    int m0 = (tile & 3) * 64, n0 = (tile >> 2) * 64;
                    float acc[2][2][4] = {};
                    tile_cp<0, 64, 0>(Zt, g_W1, SM, smu, DD, DD, m0, n0,
                                      sk * 128, sk * 128 + 128, acc);
                    float* cp = g_part + (size_t)sk * MN;
#pragma unroll
                    for (int mt = 0; mt < 2; mt++)
#pragma unroll
                        for (int nt = 0; nt < 2; nt++) {
                            int m = m0 + wm * 32 + mt * 16 + g;
                            int nn = n0 + wn * 16 + nt * 8 + q * 2;
                            *(float2*)(cp + (size_t)m * H4 + nn) =
                                make_float2(acc[mt][nt][0], acc[mt][nt][1]);
                            *(float2*)(cp + (size_t)(m + 8) * H4 + nn) =
                                make_float2(acc[mt][nt][2], acc[mt][nt][3]);
                        }
                }
            }
        }
        grid_sync(nb);
        if (step == T_) break;

        const int t = step;
        const float* Zt = g_Z + (size_t)t * NH;
        const float* Yt = g_Y + (size_t)t * NH;
        const float* Qt = g_Q + (size_t)t * NH;

        // ---- R1: a = sum(part)+b1; h = gelu(a) ----
        for (int idx = bid * 256 + tid; idx < MN; idx += nb * 256) {
            float s = 0.f;
#pragma unroll
            for (int z = 0; z < 8; z++) s += g_part[(size_t)z * MN + idx];
            s += g_b1[idx & (H4 - 1)];
            g_a[idx] = s;
            g_h[idx] = gelu_f(s);
        }
        grid_sync(nb);

        // ---- R2: dr = C2*(Zt + h@W2^T + b2 - Yt) (tf32, 128 u, 32x64) ----
        for (int u = bid; u < 128; u += nb) {
            int m0 = (u & 7) * 32, n0 = (u >> 3) * 64;
            float acc[1][2][4] = {};
            tile_cp<0, 32, 0>(g_h, g_W2, SM, smu, H4, H4, m0, n0, 0, H4, acc);
#pragma unroll
            for (int nt = 0; nt < 2; nt++) {
                int m = m0 + wm * 16 + g;
                int nn = n0 + wn * 16 + nt * 8 + q * 2;
                float2 bb = *(const float2*)(g_b2 + nn);
                {
                    float2 zz = *(const float2*)(Zt + (size_t)m * HH + nn);
                    float2 yy = *(const float2*)(Yt + (size_t)m * HH + nn);
                    *(float2*)(g_dr + (size_t)m * HH + nn) = make_float2(
                        C2 * (zz.x + acc[0][nt][0] + bb.x - yy.x),
                        C2 * (zz.y + acc[0][nt][1] + bb.y - yy.y));
                }
                {
                    int m8 = m + 8;
                    float2 zz = *(const float2*)(Zt + (size_t)m8 * HH + nn);
                    float2 yy = *(const float2*)(Yt + (size_t)m8 * HH + nn);
                    *(float2*)(g_dr + (size_t)m8 * HH + nn) = make_float2(
                        C2 * (zz.x + acc[0][nt][2] + bb.x - yy.x),
                        C2 * (zz.y + acc[0][nt][3] + bb.y - yy.y));
                }
            }
        }
        grid_sync(nb);

        // ---- R3: da_pre partials = dr @ W2 (tf32 NN, 128 u, 64x64) ----
        for (int u = bid; u < 128; u += nb) {
            int sk = u & 7, tile = u >> 3;
            int m0 = (tile & 3) * 64, n0 = (tile >> 2) * 64;
            float acc[2][2][4] = {};
            tile_cp<1, 64, 0>(g_dr, g_W2, SM, smu, HH, H4, m0, n0,
                              sk * 128, sk * 128 + 128, acc);
            float* cp = g_part + (size_t)sk * MN;
#pragma unroll
            for (int mt = 0; mt < 2; mt++)
#pragma unroll
                for (int nt = 0; nt < 2; nt++) {
                    int m = m0 + wm * 32 + mt * 16 + g;
                    int nn = n0 + wn * 16 + nt * 8 + q * 2;
                    *(float2*)(cp + (size_t)m * H4 + nn) =
                        make_float2(acc[mt][nt][0], acc[mt][nt][1]);
                    *(float2*)(cp + (size_t)(m + 8) * H4 + nn) =
                        make_float2(acc[mt][nt][2], acc[mt][nt][3]);
                }
        }
        grid_sync(nb);

        // ---- R4: da = sum(part) * gelu'(a) ----
        for (int idx = bid * 256 + tid; idx < MN; idx += nb * 256) {
            float s = 0.f;
#pragma unroll
            for (int z = 0; z < 8; z++) s += g_part[(size_t)z * MN + idx];
            g_da[idx] = s * gelu_grad(g_a[idx]);
        }
        grid_sync(nb);

        // ---- R5: weight updates (tf32 TN, 128 u, Kn=256) + biases ----
        for (int u = bid; u < 128; u += nb) {
            if (u < 64) {
                int i0 = (u & 15) * 64, j0 = (u >> 4) * 64;
                float acc[2][2][4] = {};
                tile_cp<2, 64, 0>(g_dr, g_h, SM, smu, HH, H4, i0, j0, 0, NB, acc);
#pragma unroll
                for (int mt = 0; mt < 2; mt++)
#pragma unroll
                    for (int nt = 0; nt < 2; nt++) {
                        int i = i0 + wm * 32 + mt * 16 + g;
                        int j = j0 + wn * 16 + nt * 8 + q * 2;
                        float2* p0 = (float2*)(g_W2 + (size_t)i * H4 + j);
                        float2 o0 = *p0;
                        o0.x -= LR * acc[mt][nt][0]; o0.y -= LR * acc[mt][nt][1];
                        *p0 = o0;
                        float2* p1 = (float2*)(g_W2 + (size_t)(i + 8) * H4 + j);
                        float2 o1 = *p1;
                        o1.x -= LR * acc[mt][nt][2]; o1.y -= LR * acc[mt][nt][3];
                        *p1 = o1;
                    }
            } else {
                int v = u - 64;
                int j0 = (v & 3) * 64, i0 = (v >> 2) * 64;
                float acc[2][2][4] = {};
                tile_cp<2, 64, 0>(g_da, Zt, SM, smu, H4, DD, j0, i0, 0, NB, acc);
#pragma unroll
                for (int mt = 0; mt < 2; mt++)
#pragma unroll
                    for (int nt = 0; nt < 2; nt++) {
                        int j = j0 + wm * 32 + mt * 16 + g;
                        int i = i0 + wn * 16 + nt * 8 + q * 2;
                        float2* p0 = (float2*)(g_W1 + (size_t)j * DD + i);
                        float2 o0 = *p0;
                        o0.x -= LR * acc[mt][nt][0]; o0.y -= LR * acc[mt][nt][1];
                        *p0 = o0;
                        float2* p1 = (float2*)(g_W1 + (size_t)(j + 8) * DD + i);
                        float2 o1 = *p1;
                        o1.x -= LR * acc[mt][nt][2]; o1.y -= LR * acc[mt][nt][3];
                        *p1 = o1;
                    }
            }
        }
        // bias colsums (warp-parallel, no intra-block syncs)
        for (int c = gw; c < HH; c += nb * 8) {
            float s = 0.f;
            for (int n = lane; n < NB; n += 32) s += g_dr[(size_t)n * HH + c];
#pragma unroll
            for (int o = 16; o > 0; o >>= 1) s += __shfl_xor_sync(0xffffffffu, s, o);
            if (lane == 0) g_b2[c] -= LR * s;
        }
        for (int c = gw; c < H4; c += nb * 8) {
            float s = 0.f;
            for (int n = lane; n < NB; n += 32) s += g_da[(size_t)n * H4 + c];
#pragma unroll
            for (int o = 16; o > 0; o >>= 1) s += __shfl_xor_sync(0xffffffffu, s, o);
            if (lane == 0) g_b1[c] -= LR * s;
        }
        grid_sync(nb);

        // ---- R6: a2 partials = Qt @ W1_new^T (split-tf32, 128 u, 64x64) ----
        for (int u = bid; u < 128; u += nb) {
            int sk = u & 7, tile = u >> 3;
            int m0 = (tile & 3) * 64, n0 = (tile >> 2) * 64;
            float acc[2][2][4] = {};
            tile_cp<0, 64, 1>(Qt, g_W1, SM, smu, DD, DD, m0, n0,
                              sk * 128, sk * 128 + 128, acc);
            float* cp = g_part + (size_t)sk * MN;
#pragma unroll
            for (int mt = 0; mt < 2; mt++)
#pragma unroll
                for (int nt = 0; nt < 2; nt++) {
                    int m = m0 + wm * 32 + mt * 16 + g;
                    int nn = n0 + wn * 16 + nt * 8 + q * 2;
                    *(float2*)(cp + (size_t)m * H4 + nn) =
                        make_float2(acc[mt][nt][0], acc[mt][nt][1]);
                    *(float2*)(cp + (size_t)(m + 8) * H4 + nn) =
                        make_float2(acc[mt][nt][2], acc[mt][nt][3]);
                }
        }
        grid_sync(nb);

        // ---- R7: h2 = gelu(sum(part) + b1_new) ----
        for (int idx = bid * 256 + tid; idx < MN; idx += nb * 256) {
            float s = 0.f;
#pragma unroll
            for (int z = 0; z < 8; z++) s += g_part[(size_t)z * MN + idx];
            s += g_b1[idx & (H4 - 1)];
            g_h2[idx] = gelu_f(s);
        }
        grid_sync(nb);
    }
}

// ---------------------------------------------------------------------------
// kernel_launch
// ---------------------------------------------------------------------------
extern "C" void kernel_launch(void* const* d_in, const int* in_sizes, int n_in,
                              void* d_out, int out_size)
{
    (void)in_sizes; (void)n_in; (void)out_size;
    const float* in_seq = (const float*)d_in[0];
    const float* t_k = (const float*)d_in[1];
    const float* t_v = (const float*)d_in[2];
    const float* t_q = (const float*)d_in[3];

    float *Z, *Y, *Q, *W1, *b1, *W2, *b2;
    cudaGetSymbolAddress((void**)&Z, g_Z);
    cudaGetSymbolAddress((void**)&Y, g_Y);
    cudaGetSymbolAddress((void**)&Q, g_Q);
    cudaGetSymbolAddress((void**)&W1, g_W1);
    cudaGetSymbolAddress((void**)&b1, g_b1);
    cudaGetSymbolAddress((void**)&W2, g_W2);
    cudaGetSymbolAddress((void**)&b2, g_b2);

    cudaMemcpyAsync(W1, d_in[4], sizeof(float) * H4 * HH, cudaMemcpyDeviceToDevice, 0);
    cudaMemcpyAsync(b1, d_in[5], sizeof(float) * H4, cudaMemcpyDeviceToDevice, 0);
    cudaMemcpyAsync(W2, d_in[6], sizeof(float) * HH * H4, cudaMemcpyDeviceToDevice, 0);
    cudaMemcpyAsync(b2, d_in[7], sizeof(float) * HH, cudaMemcpyDeviceToDevice, 0);

    // Phase A: tf32 tensor-core GEMMs
    const int M_big = T_ * NB;
    dim3 gA(M_big / 128, HH / 128);
    gemm_nt_tf32<<<gA, 256>>>(in_seq, t_k, Z, M_big, HH, DD);
    gemm_nt_tf32<<<gA, 256>>>(in_seq, t_v, Y, M_big, HH, DD);
    gemm_nt_tf32<<<gA, 256>>>(in_seq, t_q, Q, M_big, HH, DD);

    // Phase B: one persistent kernel, exactly one block per SM.
    int sms = 0;
    cudaDeviceGetAttribute(&sms, cudaDevAttrMultiProcessorCount, 0);
    if (sms <= 0 || sms > 148) sms = 148;
    ttt_persistent<<<sms, 256>>>((float*)d_out, sms);
}